// round 2
// baseline (speedup 1.0000x reference)
#include <cuda_runtime.h>

#define T_STEPS 512
#define BATCH   2048
#define IN_DIM  28
#define H_DIM   64
#define G_DIM   256      // 4*H
#define OUT_DIM 10
#define NB      16       // batch elements per CTA
#define NTHR    128
#define NCTA    (BATCH / NB)   // 128

// Layer-0 hidden output scratch: [T][B][H] fp32 (256 MB static device array)
__device__ float g_h1[(long long)T_STEPS * BATCH * H_DIM];

static __device__ __forceinline__ float tanh_fast(float x) {
    float y;
    asm("tanh.approx.f32 %0, %1;" : "=f"(y) : "f"(x));
    return y;
}
static __device__ __forceinline__ float sig_fast(float x) {
    return fmaf(0.5f, tanh_fast(0.5f * x), 0.5f);
}
// Packed dual fp32 FMA (Blackwell f32x2 pipe): d.lo += a.lo*b.lo ; d.hi += a.hi*b.hi
static __device__ __forceinline__ void ffma2(unsigned long long& d,
                                             unsigned long long a,
                                             unsigned long long b) {
    asm("fma.rn.f32x2 %0, %1, %2, %0;" : "+l"(d) : "l"(a), "l"(b));
}

// ---------------------------------------------------------------------------
// Layer 0: x[2048,512,28] -> h1[t,b,64] (global scratch)
// ---------------------------------------------------------------------------
__global__ void __launch_bounds__(NTHR, 1)
lstm_l0(const float* __restrict__ x,
        const float* __restrict__ Wih, const float* __restrict__ Whh,
        const float* __restrict__ bih, const float* __restrict__ bhh)
{
    constexpr int KD = IN_DIM + H_DIM;  // 92
    extern __shared__ float sm[];
    float* Ws    = sm;                   // [KD][256]  transposed weights
    float* bias  = Ws + KD * G_DIM;      // [256]
    float* xh    = bias + G_DIM;         // [KD][32]  duplicated operands {v,v}
    float* gates = xh + KD * 32;         // [256][17] padded

    const int tid = threadIdx.x;
    const int b0  = blockIdx.x * NB;

    // Load weights transposed: Ws[k][g]
    for (int i = tid; i < G_DIM * IN_DIM; i += NTHR) {
        int g = i / IN_DIM, k = i % IN_DIM;
        Ws[k * G_DIM + g] = Wih[i];
    }
    for (int i = tid; i < G_DIM * H_DIM; i += NTHR) {
        int g = i / H_DIM, k = i % H_DIM;
        Ws[(IN_DIM + k) * G_DIM + g] = Whh[i];
    }
    for (int g = tid; g < G_DIM; g += NTHR) bias[g] = bih[g] + bhh[g];
    // h rows (28..91) start at zero
    for (int i = tid; i < H_DIM * 32; i += NTHR) xh[IN_DIM * 32 + i] = 0.0f;
    __syncthreads();

    const int gg = tid >> 2;   // gate octet 0..31 -> gates [8gg, 8gg+8)
    const int bb = tid & 3;    // batch quad -> b in [4bb, 4bb+4)
    const int uu = tid & 63;   // cell-update hidden unit
    const int cb = tid >> 6;   // cell-update batch base (0/1)

    unsigned long long bias_p[4];
#pragma unroll
    for (int p = 0; p < 4; p++)
        bias_p[p] = *reinterpret_cast<const unsigned long long*>(bias + gg * 8 + p * 2);

    float c[8];
#pragma unroll
    for (int j = 0; j < 8; j++) c[j] = 0.0f;

    // prefetch x_0
    float xr[4];
#pragma unroll
    for (int j = 0; j < 4; j++) {
        int idx = tid + j * NTHR;
        if (idx < NB * IN_DIM) {
            int bl = idx / IN_DIM, k = idx % IN_DIM;
            xr[j] = x[((long long)(b0 + bl) * T_STEPS) * IN_DIM + k];
        }
    }

    for (int t = 0; t < T_STEPS; t++) {
        // write x_t duplicated into xh rows 0..27
#pragma unroll
        for (int j = 0; j < 4; j++) {
            int idx = tid + j * NTHR;
            if (idx < NB * IN_DIM) {
                int bl = idx / IN_DIM, k = idx % IN_DIM;
                xh[k * 32 + 2 * bl]     = xr[j];
                xh[k * 32 + 2 * bl + 1] = xr[j];
            }
        }
        __syncthreads();   // x_t + h_{t-1} visible

        // prefetch x_{t+1} (latency hidden under gate GEMM)
        if (t + 1 < T_STEPS) {
#pragma unroll
            for (int j = 0; j < 4; j++) {
                int idx = tid + j * NTHR;
                if (idx < NB * IN_DIM) {
                    int bl = idx / IN_DIM, k = idx % IN_DIM;
                    xr[j] = x[((long long)(b0 + bl) * T_STEPS + (t + 1)) * IN_DIM + k];
                }
            }
        }

        // gate GEMM: 8 gates x 4 batch per thread, packed pairs along gates
        unsigned long long acc[4][4];
#pragma unroll
        for (int p = 0; p < 4; p++)
#pragma unroll
            for (int q = 0; q < 4; q++) acc[p][q] = bias_p[p];

#pragma unroll 4
        for (int k = 0; k < KD; k++) {
            const float* wr = Ws + k * G_DIM + gg * 8;
            ulonglong2 wv0 = *reinterpret_cast<const ulonglong2*>(wr);
            ulonglong2 wv1 = *reinterpret_cast<const ulonglong2*>(wr + 4);
            const float* xp = xh + k * 32 + bb * 8;
            ulonglong2 xv0 = *reinterpret_cast<const ulonglong2*>(xp);
            ulonglong2 xv1 = *reinterpret_cast<const ulonglong2*>(xp + 4);
            unsigned long long w[4]  = {wv0.x, wv0.y, wv1.x, wv1.y};
            unsigned long long xd[4] = {xv0.x, xv0.y, xv1.x, xv1.y};
#pragma unroll
            for (int p = 0; p < 4; p++)
#pragma unroll
                for (int q = 0; q < 4; q++)
                    ffma2(acc[p][q], w[p], xd[q]);
        }

#pragma unroll
        for (int p = 0; p < 4; p++)
#pragma unroll
            for (int q = 0; q < 4; q++) {
                float2 v = *reinterpret_cast<float2*>(&acc[p][q]);
                int g = gg * 8 + 2 * p;
                int b = bb * 4 + q;
                gates[g * 17 + b]       = v.x;
                gates[(g + 1) * 17 + b] = v.y;
            }
        __syncthreads();   // gates visible

        // LSTM cell update (c in regs), write h_t dup + to global scratch
#pragma unroll
        for (int j = 0; j < 8; j++) {
            int b = cb + 2 * j;
            float gi = gates[(uu      ) * 17 + b];
            float gf = gates[(uu +  64) * 17 + b];
            float gc = gates[(uu + 128) * 17 + b];
            float go = gates[(uu + 192) * 17 + b];
            float iv = sig_fast(gi);
            float fv = sig_fast(gf);
            float gv = tanh_fast(gc);
            float ov = sig_fast(go);
            float cn = fmaf(fv, c[j], iv * gv);
            c[j] = cn;
            float h = ov * tanh_fast(cn);
            xh[(IN_DIM + uu) * 32 + 2 * b]     = h;
            xh[(IN_DIM + uu) * 32 + 2 * b + 1] = h;
            g_h1[((long long)t * BATCH + b0 + b) * H_DIM + uu] = h;
        }
        // no sync needed: next x-write hits rows 0..27 (disjoint from h rows),
        // and next syncthreads orders h writes before gate reads.
    }
}

// ---------------------------------------------------------------------------
// Layer 1: h1 (scratch) -> h2; epilogue writes out[2048,10] and r_last[2048,64]
// ---------------------------------------------------------------------------
__global__ void __launch_bounds__(NTHR, 1)
lstm_l1(const float* __restrict__ Wih, const float* __restrict__ Whh,
        const float* __restrict__ bih, const float* __restrict__ bhh,
        const float* __restrict__ Wout, const float* __restrict__ bout,
        float* __restrict__ dout)
{
    constexpr int KD = H_DIM + H_DIM;   // 128
    extern __shared__ float sm[];
    float* Ws    = sm;                   // [128][256]
    float* bias  = Ws + KD * G_DIM;
    float* xh    = bias + G_DIM;         // [128][32]: rows 0..63 h1, 64..127 h2
    float* gates = xh + KD * 32;         // [256][17]

    const int tid = threadIdx.x;
    const int b0  = blockIdx.x * NB;

    for (int i = tid; i < G_DIM * H_DIM; i += NTHR) {
        int g = i / H_DIM, k = i % H_DIM;
        Ws[k * G_DIM + g] = Wih[i];
    }
    for (int i = tid; i < G_DIM * H_DIM; i += NTHR) {
        int g = i / H_DIM, k = i % H_DIM;
        Ws[(H_DIM + k) * G_DIM + g] = Whh[i];
    }
    for (int g = tid; g < G_DIM; g += NTHR) bias[g] = bih[g] + bhh[g];
    for (int i = tid; i < H_DIM * 32; i += NTHR) xh[H_DIM * 32 + i] = 0.0f;
    __syncthreads();

    const int gg = tid >> 2;
    const int bb = tid & 3;
    const int uu = tid & 63;
    const int cb = tid >> 6;

    unsigned long long bias_p[4];
#pragma unroll
    for (int p = 0; p < 4; p++)
        bias_p[p] = *reinterpret_cast<const unsigned long long*>(bias + gg * 8 + p * 2);

    float c[8];
#pragma unroll
    for (int j = 0; j < 8; j++) c[j] = 0.0f;

    // prefetch h1_0
    float hr[8];
#pragma unroll
    for (int j = 0; j < 8; j++) {
        int idx = tid + j * NTHR;
        int bl = idx >> 6, u = idx & 63;
        hr[j] = g_h1[(long long)(b0 + bl) * H_DIM + u];
    }

    for (int t = 0; t < T_STEPS; t++) {
#pragma unroll
        for (int j = 0; j < 8; j++) {
            int idx = tid + j * NTHR;
            int bl = idx >> 6, u = idx & 63;
            xh[u * 32 + 2 * bl]     = hr[j];
            xh[u * 32 + 2 * bl + 1] = hr[j];
        }
        __syncthreads();

        if (t + 1 < T_STEPS) {
#pragma unroll
            for (int j = 0; j < 8; j++) {
                int idx = tid + j * NTHR;
                int bl = idx >> 6, u = idx & 63;
                hr[j] = g_h1[((long long)(t + 1) * BATCH + b0 + bl) * H_DIM + u];
            }
        }

        unsigned long long acc[4][4];
#pragma unroll
        for (int p = 0; p < 4; p++)
#pragma unroll
            for (int q = 0; q < 4; q++) acc[p][q] = bias_p[p];

#pragma unroll 4
        for (int k = 0; k < KD; k++) {
            const float* wr = Ws + k * G_DIM + gg * 8;
            ulonglong2 wv0 = *reinterpret_cast<const ulonglong2*>(wr);
            ulonglong2 wv1 = *reinterpret_cast<const ulonglong2*>(wr + 4);
            const float* xp = xh + k * 32 + bb * 8;
            ulonglong2 xv0 = *reinterpret_cast<const ulonglong2*>(xp);
            ulonglong2 xv1 = *reinterpret_cast<const ulonglong2*>(xp + 4);
            unsigned long long w[4]  = {wv0.x, wv0.y, wv1.x, wv1.y};
            unsigned long long xd[4] = {xv0.x, xv0.y, xv1.x, xv1.y};
#pragma unroll
            for (int p = 0; p < 4; p++)
#pragma unroll
                for (int q = 0; q < 4; q++)
                    ffma2(acc[p][q], w[p], xd[q]);
        }

#pragma unroll
        for (int p = 0; p < 4; p++)
#pragma unroll
            for (int q = 0; q < 4; q++) {
                float2 v = *reinterpret_cast<float2*>(&acc[p][q]);
                int g = gg * 8 + 2 * p;
                int b = bb * 4 + q;
                gates[g * 17 + b]       = v.x;
                gates[(g + 1) * 17 + b] = v.y;
            }
        __syncthreads();

#pragma unroll
        for (int j = 0; j < 8; j++) {
            int b = cb + 2 * j;
            float gi = gates[(uu      ) * 17 + b];
            float gf = gates[(uu +  64) * 17 + b];
            float gc = gates[(uu + 128) * 17 + b];
            float go = gates[(uu + 192) * 17 + b];
            float iv = sig_fast(gi);
            float fv = sig_fast(gf);
            float gv = tanh_fast(gc);
            float ov = sig_fast(go);
            float cn = fmaf(fv, c[j], iv * gv);
            c[j] = cn;
            float h = ov * tanh_fast(cn);
            xh[(H_DIM + uu) * 32 + 2 * b]     = h;
            xh[(H_DIM + uu) * 32 + 2 * b + 1] = h;
        }
    }
    __syncthreads();   // final h2 visible to all threads

    // r_last -> dout[BATCH*OUT_DIM ...]
#pragma unroll
    for (int j = 0; j < 8; j++) {
        int idx = tid + j * NTHR;
        int bl = idx >> 6, u = idx & 63;
        dout[(long long)BATCH * OUT_DIM + (long long)(b0 + bl) * H_DIM + u] =
            xh[(H_DIM + u) * 32 + 2 * bl];
    }
    // out = h2 @ Wout^T + bout -> dout[0 .. BATCH*OUT_DIM)
    // FIX: grid-stride loop (NB*OUT_DIM = 160 > NTHR = 128; the old guarded
    // `if (tid < 160)` left 20% of `out` unwritten -> rel_err sqrt(0.2)=0.447)
    for (int i = tid; i < NB * OUT_DIM; i += NTHR) {
        int bl = i / OUT_DIM, o = i % OUT_DIM;
        float s = bout[o];
#pragma unroll
        for (int u = 0; u < H_DIM; u++)
            s = fmaf(xh[(H_DIM + u) * 32 + 2 * bl], Wout[o * H_DIM + u], s);
        dout[(long long)(b0 + bl) * OUT_DIM + o] = s;
    }
}

// ---------------------------------------------------------------------------
extern "C" void kernel_launch(void* const* d_in, const int* in_sizes, int n_in,
                              void* d_out, int out_size)
{
    const float* x    = (const float*)d_in[0];
    const float* Wih0 = (const float*)d_in[1];
    const float* Whh0 = (const float*)d_in[2];
    const float* bih0 = (const float*)d_in[3];
    const float* bhh0 = (const float*)d_in[4];
    const float* Wih1 = (const float*)d_in[5];
    const float* Whh1 = (const float*)d_in[6];
    const float* bih1 = (const float*)d_in[7];
    const float* bhh1 = (const float*)d_in[8];
    const float* Wout = (const float*)d_in[9];
    const float* bout = (const float*)d_in[10];
    float* out = (float*)d_out;

    const int smA = ((IN_DIM + H_DIM) * G_DIM + G_DIM + (IN_DIM + H_DIM) * 32 + G_DIM * 17) * 4;
    const int smB = ((H_DIM + H_DIM) * G_DIM + G_DIM + (H_DIM + H_DIM) * 32 + G_DIM * 17) * 4;

    cudaFuncSetAttribute(lstm_l0, cudaFuncAttributeMaxDynamicSharedMemorySize, smA);
    cudaFuncSetAttribute(lstm_l1, cudaFuncAttributeMaxDynamicSharedMemorySize, smB);

    lstm_l0<<<NCTA, NTHR, smA>>>(x, Wih0, Whh0, bih0, bhh0);
    lstm_l1<<<NCTA, NTHR, smB>>>(Wih1, Whh1, bih1, bhh1, Wout, bout, out);
}